// round 1
// baseline (speedup 1.0000x reference)
#include <cuda_runtime.h>
#include <cstdint>

#define NN 50000
#define NE 800000
#define DIM 128
#define KC 5000

// ---------------- scratch (static device globals; no allocation) -------------
__device__ float g_h1[NN * DIM];
__device__ float g_x1[NN * DIM];
__device__ float g_x1g[NN * DIM];
__device__ unsigned g_ukey[NN];
__device__ int g_keep[NN];
__device__ int g_cid[NN];
__device__ int g_degin[NN];
__device__ int g_deg2[NN];
__device__ float g_dinv[NN];
__device__ int g_off1[NN + 1];
__device__ int g_cur1[NN];
__device__ int g_csr1[NE];
__device__ unsigned long long g_bestkey[NN];
__device__ float g_sums[KC * DIM];
__device__ float g_cntf[KC];
__device__ float g_xp[KC * DIM];
__device__ float g_h2[KC * DIM];
__device__ float g_xp2[KC * DIM];
__device__ int g_degc[KC];
__device__ float g_dinvc[KC];
__device__ int g_off2[KC + 1];
__device__ int g_cur2[KC];
__device__ int g_csr2[NE];
__device__ unsigned g_hist[256];
__device__ unsigned g_prefix;
__device__ int g_need;
__device__ int g_cnteq;
__device__ unsigned long long g_fbkey;
__device__ int g_kctr;
__device__ int g_maxdeg;

// ---------------- init / zero ------------------------------------------------
__global__ void k_zero() {
    int i = blockIdx.x * blockDim.x + threadIdx.x;
    if (i < NN) { g_degin[i] = 0; g_deg2[i] = 0; g_cur1[i] = 0; g_bestkey[i] = 0ULL; }
    if (i < KC) { g_cntf[i] = 0.f; g_degc[i] = 0; g_cur2[i] = 0; }
    if (i < KC * DIM) g_sums[i] = 0.f;
    if (i < 256) g_hist[i] = 0u;
    if (i == 0) {
        g_prefix = 0u; g_need = KC; g_cnteq = 0;
        g_fbkey = 0ULL; g_kctr = 0; g_maxdeg = 0;
    }
}

// ---------------- degrees ----------------------------------------------------
__global__ void k_deg(const int* __restrict__ row, const int* __restrict__ col) {
    int e = blockIdx.x * blockDim.x + threadIdx.x;
    if (e >= NE) return;
    atomicAdd(&g_degin[col[e]], 1);
    atomicAdd(&g_deg2[row[e]], 1);
}

__global__ void k_dinv() {
    int i = blockIdx.x * blockDim.x + threadIdx.x;
    if (i < NN) g_dinv[i] = rsqrtf((float)g_degin[i] + 1.0f);
}

// ---------------- generic single-block exclusive scan -------------------------
__global__ void k_scan(const int* __restrict__ in, int* __restrict__ out, int n) {
    const int TPB = 1024, PER = 8, CH = TPB * PER;
    __shared__ int wsum[32];
    __shared__ int carry_s;
    int tid = threadIdx.x, lane = tid & 31, w = tid >> 5;
    if (tid == 0) carry_s = 0;
    __syncthreads();
    for (int base = 0; base < n; base += CH) {
        int v[PER]; int s = 0;
#pragma unroll
        for (int p = 0; p < PER; p++) {
            int i = base + tid * PER + p;
            v[p] = (i < n) ? in[i] : 0;
            s += v[p];
        }
        int sc = s;
#pragma unroll
        for (int o = 1; o < 32; o <<= 1) {
            int t = __shfl_up_sync(0xffffffffu, sc, o);
            if (lane >= o) sc += t;
        }
        if (lane == 31) wsum[w] = sc;
        __syncthreads();
        if (w == 0) {
            int ws = wsum[lane];
#pragma unroll
            for (int o = 1; o < 32; o <<= 1) {
                int t = __shfl_up_sync(0xffffffffu, ws, o);
                if (lane >= o) ws += t;
            }
            wsum[lane] = ws;
        }
        __syncthreads();
        int excl = carry_s + (w ? wsum[w - 1] : 0) + sc - s;
#pragma unroll
        for (int p = 0; p < PER; p++) {
            int i = base + tid * PER + p;
            if (i < n) out[i] = excl;
            excl += v[p];
        }
        __syncthreads();
        if (tid == 0) carry_s += wsum[31];
        __syncthreads();
    }
    if (tid == 0) out[n] = carry_s;
}

// ---------------- CSR scatter (group edges by col) ----------------------------
__global__ void k_scat1(const int* __restrict__ row, const int* __restrict__ col) {
    int e = blockIdx.x * blockDim.x + threadIdx.x;
    if (e >= NE) return;
    int c = col[e];
    int p = g_off1[c] + atomicAdd(&g_cur1[c], 1);
    g_csr1[p] = row[e];
}

// ---------------- fp32 SMEM-tiled GEMM: C[M,128] = A[M,128] @ W[128,128] ------
// optional epilogue: + bias[col] + bcast[cid[row]*128 + col]
__global__ void __launch_bounds__(256) k_gemm(
    const float* __restrict__ A, const float* __restrict__ W,
    float* __restrict__ C, int M,
    const float* __restrict__ bias,
    const float* __restrict__ bcast, const int* __restrict__ cid)
{
    __shared__ float As[64][17];
    __shared__ float Ws[16][128];
    int tid = threadIdx.x;
    int tx = tid & 15, ty = tid >> 4;
    int row0 = blockIdx.x * 64;
    float acc[4][8];
#pragma unroll
    for (int i = 0; i < 4; i++)
#pragma unroll
        for (int j = 0; j < 8; j++) acc[i][j] = 0.f;

    for (int kt = 0; kt < 128; kt += 16) {
#pragma unroll
        for (int it = 0; it < 4; it++) {
            int idx = tid + it * 256;
            int k = idx & 15, r = idx >> 4;
            int gr = row0 + r;
            As[r][k] = (gr < M) ? A[gr * 128 + kt + k] : 0.f;
        }
#pragma unroll
        for (int it = 0; it < 2; it++) {
            int idx = tid + it * 256;
            int k = idx >> 5, n4 = idx & 31;
            float4 wv = *(const float4*)&W[(kt + k) * 128 + n4 * 4];
            *(float4*)&Ws[k][n4 * 4] = wv;
        }
        __syncthreads();
#pragma unroll
        for (int kk = 0; kk < 16; kk++) {
            float av[4];
#pragma unroll
            for (int i = 0; i < 4; i++) av[i] = As[ty * 4 + i][kk];
            float4 w0 = *(const float4*)&Ws[kk][tx * 8];
            float4 w1 = *(const float4*)&Ws[kk][tx * 8 + 4];
            float wv[8] = {w0.x, w0.y, w0.z, w0.w, w1.x, w1.y, w1.z, w1.w};
#pragma unroll
            for (int i = 0; i < 4; i++)
#pragma unroll
                for (int j = 0; j < 8; j++) acc[i][j] += av[i] * wv[j];
        }
        __syncthreads();
    }
#pragma unroll
    for (int i = 0; i < 4; i++) {
        int r = row0 + ty * 4 + i;
        if (r >= M) continue;
        const float* bc = bcast ? &bcast[cid[r] * 128] : nullptr;
#pragma unroll
        for (int j = 0; j < 8; j++) {
            int c = tx * 8 + j;
            float v = acc[i][j];
            if (bias) v += bias[c];
            if (bc) v += bc[c];
            C[r * 128 + c] = v;
        }
    }
}

// ---------------- conv1 gather + score/gate fusion ----------------------------
__global__ void k_conv1(const float* __restrict__ b1, const float* __restrict__ wsc) {
    int c = blockIdx.x;
    int t = threadIdx.x;       // 128 threads
    float dc = g_dinv[c];
    float acc = 0.f;
    int s0 = g_off1[c], s1 = g_off1[c + 1];
    for (int e = s0; e < s1; e++) {
        int s = g_csr1[e];
        acc += g_dinv[s] * g_h1[s * DIM + t];
    }
    float x = dc * acc + dc * dc * g_h1[c * DIM + t] + b1[t];
    float x1 = fmaxf(x, 0.f);
    // raw = x1 . w_score (block reduction over 128)
    float p = x1 * wsc[t];
#pragma unroll
    for (int o = 16; o; o >>= 1) p += __shfl_xor_sync(0xffffffffu, p, o);
    __shared__ float sp[4];
    __shared__ float sg;
    if ((t & 31) == 0) sp[t >> 5] = p;
    __syncthreads();
    if (t == 0) {
        float raw = sp[0] + sp[1] + sp[2] + sp[3];
        sg = tanhf(raw);
        unsigned ub = __float_as_uint(raw);
        ub = (ub & 0x80000000u) ? ~ub : (ub | 0x80000000u);
        g_ukey[c] = ub;
    }
    __syncthreads();
    g_x1[c * DIM + t] = x1;
    g_x1g[c * DIM + t] = x1 * sg;
}

// ---------------- radix select (K-th largest orderable key) -------------------
__global__ void k_hist(int shift, int pass) {
    int i = blockIdx.x * blockDim.x + threadIdx.x;
    if (i >= NN) return;
    unsigned u = g_ukey[i];
    if (pass == 0 || (u >> (shift + 8)) == g_prefix)
        atomicAdd(&g_hist[(u >> shift) & 255u], 1u);
}

__global__ void k_select(int last) {
    __shared__ unsigned sh[256];
    int t = threadIdx.x;
    sh[t] = g_hist[t];
    __syncthreads();
    if (t == 0) {
        int need = g_need;
        unsigned cum = 0;
        for (int d = 255; d >= 0; d--) {
            unsigned h = sh[d];
            if (cum + h >= (unsigned)need) {
                g_prefix = (g_prefix << 8) | (unsigned)d;
                g_need = need - (int)cum;
                if (last) g_cnteq = (int)h;
                break;
            }
            cum += h;
        }
    }
    __syncthreads();
    g_hist[t] = 0u;   // reset for next pass / next replay
}

__global__ void k_keep() {
    int i = blockIdx.x * blockDim.x + threadIdx.x;
    if (i >= NN) return;
    unsigned u = g_ukey[i], T = g_prefix;
    g_keep[i] = (u > T) || (u == T && g_cnteq == g_need);
}

// rare path: index-ordered selection among ties (exactly matches jax top_k ties)
__global__ void k_ties() {
    if (g_cnteq == g_need) return;
    unsigned T = g_prefix;
    int need = g_need;
    __shared__ int wsum[32];
    __shared__ int scarry;
    int tid = threadIdx.x, lane = tid & 31, w = tid >> 5;
    if (tid == 0) scarry = 0;
    __syncthreads();
    for (int base = 0; base < NN; base += 1024) {
        int i = base + tid;
        int istie = (i < NN && g_ukey[i] == T) ? 1 : 0;
        unsigned m = __ballot_sync(0xffffffffu, istie);
        int excl = __popc(m & ((1u << lane) - 1u));
        if (lane == 0) wsum[w] = __popc(m);
        __syncthreads();
        int wbase = 0;
        for (int ww = 0; ww < w; ww++) wbase += wsum[ww];
        int rank = scarry + wbase + excl;
        if (istie && rank < need) g_keep[i] = 1;
        __syncthreads();
        if (tid == 0) {
            int tot = 0;
            for (int ww = 0; ww < 32; ww++) tot += wsum[ww];
            scarry += tot;
        }
        __syncthreads();
    }
}

// ---------------- cluster ids / fallback / best neighbor ----------------------
__global__ void k_ids() {
    int i = blockIdx.x * blockDim.x + threadIdx.x;
    if (i >= NN) return;
    if (g_keep[i]) {
        g_cid[i] = atomicAdd(&g_kctr, 1);
        atomicMax(&g_maxdeg, g_deg2[i]);
    } else g_cid[i] = -1;
}

__global__ void k_fb() {
    int i = blockIdx.x * blockDim.x + threadIdx.x;
    if (i >= NN) return;
    if (g_keep[i] && g_deg2[i] == g_maxdeg) {
        unsigned long long key =
            ((unsigned long long)g_ukey[i] << 17) | (unsigned long long)(0x1FFFFu - (unsigned)i);
        atomicMax(&g_fbkey, key);
    }
}

__global__ void k_bn(const int* __restrict__ row, const int* __restrict__ col) {
    int j = blockIdx.x * blockDim.x + threadIdx.x;
    if (j >= 2 * NE) return;
    int owner, neigh; unsigned ord;
    if (j < NE) { owner = row[j]; neigh = col[j]; ord = 2u * (unsigned)j; }
    else { int e = j - NE; owner = col[e]; neigh = row[e]; ord = 2u * (unsigned)e + 1u; }
    if (g_keep[neigh]) {
        unsigned long long key = ((unsigned long long)g_deg2[neigh] << 38)
            | ((unsigned long long)(0x1FFFFFu - ord) << 17)
            | (unsigned long long)(unsigned)neigh;
        atomicMax(&g_bestkey[owner], key);
    }
}

__global__ void k_assign() {
    int i = blockIdx.x * blockDim.x + threadIdx.x;
    if (i >= NN) return;
    if (!g_keep[i]) {
        unsigned long long key = g_bestkey[i];
        if (key) {
            g_cid[i] = g_cid[(int)(key & 0x1FFFFULL)];
        } else {
            int fnode = 0x1FFFF - (int)(g_fbkey & 0x1FFFFULL);
            g_cid[i] = g_cid[fnode];
        }
    }
}

// ---------------- pooling ------------------------------------------------------
__global__ void k_pool() {
    int i = blockIdx.x;
    int t = threadIdx.x;
    int c = g_cid[i];
    atomicAdd(&g_sums[c * DIM + t], g_x1g[i * DIM + t]);
    if (t == 0) atomicAdd(&g_cntf[c], 1.f);
}

__global__ void k_xp() {
    int idx = blockIdx.x * blockDim.x + threadIdx.x;
    if (idx >= KC * DIM) return;
    int c = idx >> 7;
    g_xp[idx] = g_sums[idx] / fmaxf(g_cntf[c], 1.f);
}

// ---------------- coarse graph (conv2) -----------------------------------------
__global__ void k_degc(const int* __restrict__ row, const int* __restrict__ col) {
    int e = blockIdx.x * blockDim.x + threadIdx.x;
    if (e >= NE) return;
    int cu = g_cid[row[e]], cv = g_cid[col[e]];
    if (cu != cv) atomicAdd(&g_degc[cv], 1);
}

__global__ void k_dinvc() {
    int c = blockIdx.x * blockDim.x + threadIdx.x;
    if (c < KC) g_dinvc[c] = rsqrtf((float)g_degc[c] + 1.0f);
}

__global__ void k_scat2(const int* __restrict__ row, const int* __restrict__ col) {
    int e = blockIdx.x * blockDim.x + threadIdx.x;
    if (e >= NE) return;
    int cu = g_cid[row[e]], cv = g_cid[col[e]];
    if (cu != cv) {
        int p = g_off2[cv] + atomicAdd(&g_cur2[cv], 1);
        g_csr2[p] = cu;
    }
}

__global__ void k_conv2(const float* __restrict__ b2) {
    int c = blockIdx.x;
    int t = threadIdx.x;
    float dc = g_dinvc[c];
    float acc = 0.f;
    int s0 = g_off2[c], s1 = g_off2[c + 1];
    for (int e = s0; e < s1; e++) {
        int s = g_csr2[e];
        acc += g_dinvc[s] * g_h2[s * DIM + t];
    }
    g_xp2[c * DIM + t] = dc * acc + dc * dc * g_h2[c * DIM + t] + b2[t];
}

// ---------------- tail: zero anything beyond logits (scalar aux output) ---------
__global__ void k_tail(float* __restrict__ out, int start, int total) {
    int i = start + blockIdx.x * blockDim.x + threadIdx.x;
    if (i < total) out[i] = 0.f;
}

// ================================================================================
extern "C" void kernel_launch(void* const* d_in, const int* in_sizes, int n_in,
                              void* d_out, int out_size) {
    const float* x   = (const float*)d_in[0];
    const int*   ei  = (const int*)d_in[1];
    const int*   row = ei;
    const int*   col = ei + NE;
    const float* W1  = (const float*)d_in[2];
    const float* b1  = (const float*)d_in[3];
    const float* W2  = (const float*)d_in[4];
    const float* b2  = (const float*)d_in[5];
    const float* wsc = (const float*)d_in[6];
    const float* Wsk = (const float*)d_in[7];
    const float* bsk = (const float*)d_in[8];
    float* out = (float*)d_out;

    // device pointers to scratch (pure lookups; capture-safe, no allocation)
    float *p_h1, *p_x1, *p_xp, *p_h2, *p_xp2;
    int *p_degin, *p_off1, *p_degc, *p_off2, *p_cid;
    cudaGetSymbolAddress((void**)&p_h1, g_h1);
    cudaGetSymbolAddress((void**)&p_x1, g_x1);
    cudaGetSymbolAddress((void**)&p_xp, g_xp);
    cudaGetSymbolAddress((void**)&p_h2, g_h2);
    cudaGetSymbolAddress((void**)&p_xp2, g_xp2);
    cudaGetSymbolAddress((void**)&p_degin, g_degin);
    cudaGetSymbolAddress((void**)&p_off1, g_off1);
    cudaGetSymbolAddress((void**)&p_degc, g_degc);
    cudaGetSymbolAddress((void**)&p_off2, g_off2);
    cudaGetSymbolAddress((void**)&p_cid, g_cid);

    const int TB = 256;
    k_zero<<<(KC * DIM + TB - 1) / TB, TB>>>();
    k_deg<<<(NE + TB - 1) / TB, TB>>>(row, col);
    k_dinv<<<(NN + TB - 1) / TB, TB>>>();

    // h1 = x @ W1
    k_gemm<<<(NN + 63) / 64, 256>>>(x, W1, p_h1, NN, nullptr, nullptr, nullptr);

    // CSR by col
    k_scan<<<1, 1024>>>(p_degin, p_off1, NN);
    k_scat1<<<(NE + TB - 1) / TB, TB>>>(row, col);

    // conv1 + relu + score + gate (writes x1, x1g, orderable keys)
    k_conv1<<<NN, 128>>>(b1, wsc);

    // radix-select K-th largest key
    for (int p = 0; p < 4; p++) {
        k_hist<<<(NN + TB - 1) / TB, TB>>>(24 - 8 * p, p);
        k_select<<<1, 256>>>(p == 3 ? 1 : 0);
    }
    k_keep<<<(NN + TB - 1) / TB, TB>>>();
    k_ties<<<1, 1024>>>();

    k_ids<<<(NN + TB - 1) / TB, TB>>>();
    k_fb<<<(NN + TB - 1) / TB, TB>>>();
    k_bn<<<(2 * NE + TB - 1) / TB, TB>>>(row, col);
    k_assign<<<(NN + TB - 1) / TB, TB>>>();

    // mean pool
    k_pool<<<NN, 128>>>();
    k_xp<<<(KC * DIM + TB - 1) / TB, TB>>>();

    // coarse graph degrees + CSR
    k_degc<<<(NE + TB - 1) / TB, TB>>>(row, col);
    k_dinvc<<<(KC + TB - 1) / TB, TB>>>();
    k_scan<<<1, 1024>>>(p_degc, p_off2, KC);
    k_scat2<<<(NE + TB - 1) / TB, TB>>>(row, col);

    // h2 = x_p @ W2 ; conv2
    k_gemm<<<(KC + 63) / 64, 256>>>(p_xp, W2, p_h2, KC, nullptr, nullptr, nullptr);
    k_conv2<<<KC, 128>>>(b2);

    // logits = x1 @ W_skip + b_skip + x_p2[cid]
    k_gemm<<<(NN + 63) / 64, 256>>>(p_x1, Wsk, out, NN, bsk, p_xp2, p_cid);

    // aux scalar output (0.0) / any trailing elements
    int tail = out_size - NN * DIM;
    if (tail > 0)
        k_tail<<<(tail + TB - 1) / TB, TB>>>(out, NN * DIM, out_size);
}